// round 11
// baseline (speedup 1.0000x reference)
#include <cuda_runtime.h>
#include <cstdint>

#define Bq 4
#define Hh 8
#define Nn 1024
#define Dd 64
#define DIMM 512
#define BH (Bq*Hh)
#define QT 8

// scratch (8 MB each)
__device__ float g_Q [BH*Nn*Dd];
__device__ float g_Kt[BH*Dd*Nn];
__device__ float g_V [BH*Nn*Dd];
__device__ float g_O [Bq*Nn*DIMM];

// ---------------------------------------------------------------------------
// GEMM1: qkv = X(4096x512) @ Wqkv(512x1536), scattered into Q / K^T / V
// ---------------------------------------------------------------------------
__global__ __launch_bounds__(256) void qkv_gemm(const float* __restrict__ X,
                                                const float* __restrict__ W)
{
    __shared__ float As[8][128];
    __shared__ float Bs[8][128];
    const int t = threadIdx.x;
    const int row0 = blockIdx.y * 128;
    const int col0 = blockIdx.x * 128;
    const int tx = t & 15, ty = t >> 4;
    const int am = t >> 1, ak = (t & 1) * 4;
    const int bk = t >> 5, bn = (t & 31) * 4;

    float c[8][8];
#pragma unroll
    for (int i = 0; i < 8; i++)
#pragma unroll
        for (int j = 0; j < 8; j++) c[i][j] = 0.f;

    for (int k0 = 0; k0 < 512; k0 += 8) {
        float4 av = *(const float4*)&X[(row0 + am) * 512 + k0 + ak];
        float4 bv = *(const float4*)&W[(k0 + bk) * 1536 + col0 + bn];
        __syncthreads();
        As[ak + 0][am] = av.x; As[ak + 1][am] = av.y;
        As[ak + 2][am] = av.z; As[ak + 3][am] = av.w;
        *(float4*)&Bs[bk][bn] = bv;
        __syncthreads();
#pragma unroll
        for (int kk = 0; kk < 8; kk++) {
            float ra[8], rb[8];
            *(float4*)&ra[0] = *(float4*)&As[kk][ty * 8];
            *(float4*)&ra[4] = *(float4*)&As[kk][ty * 8 + 4];
            *(float4*)&rb[0] = *(float4*)&Bs[kk][tx * 8];
            *(float4*)&rb[4] = *(float4*)&Bs[kk][tx * 8 + 4];
#pragma unroll
            for (int i = 0; i < 8; i++)
#pragma unroll
                for (int j = 0; j < 8; j++) c[i][j] += ra[i] * rb[j];
        }
    }

    const int part = col0 >> 9;   // uniform per block (128 | 512)
#pragma unroll
    for (int i = 0; i < 8; i++) {
        int grow = row0 + ty * 8 + i;
        int b = grow >> 10, n = grow & 1023;
#pragma unroll
        for (int j = 0; j < 8; j++) {
            int col = col0 + tx * 8 + j;
            int h = (col >> 6) & 7;
            int d = col & 63;
            int bh = b * 8 + h;
            float v = c[i][j];
            if (part == 0)      g_Q [(bh * 1024 + n) * 64 + d]  = v;
            else if (part == 1) g_Kt[(bh * 64 + d) * 1024 + n]  = v;
            else                g_V [(bh * 1024 + n) * 64 + d]  = v;
        }
    }
}

// ---------------------------------------------------------------------------
// GEMM2: out = O(4096x512) @ Wout(512x512) + b_out
// ---------------------------------------------------------------------------
__global__ __launch_bounds__(256) void out_gemm(const float* __restrict__ W,
                                                const float* __restrict__ bias,
                                                float* __restrict__ out)
{
    __shared__ float As[8][128];
    __shared__ float Bs[8][128];
    const int t = threadIdx.x;
    const int row0 = blockIdx.y * 128;
    const int col0 = blockIdx.x * 128;
    const int tx = t & 15, ty = t >> 4;
    const int am = t >> 1, ak = (t & 1) * 4;
    const int bk = t >> 5, bn = (t & 31) * 4;

    float c[8][8];
#pragma unroll
    for (int i = 0; i < 8; i++)
#pragma unroll
        for (int j = 0; j < 8; j++) c[i][j] = 0.f;

    for (int k0 = 0; k0 < 512; k0 += 8) {
        float4 av = *(const float4*)&g_O[(row0 + am) * 512 + k0 + ak];
        float4 bv = *(const float4*)&W[(k0 + bk) * 512 + col0 + bn];
        __syncthreads();
        As[ak + 0][am] = av.x; As[ak + 1][am] = av.y;
        As[ak + 2][am] = av.z; As[ak + 3][am] = av.w;
        *(float4*)&Bs[bk][bn] = bv;
        __syncthreads();
#pragma unroll
        for (int kk = 0; kk < 8; kk++) {
            float ra[8], rb[8];
            *(float4*)&ra[0] = *(float4*)&As[kk][ty * 8];
            *(float4*)&ra[4] = *(float4*)&As[kk][ty * 8 + 4];
            *(float4*)&rb[0] = *(float4*)&Bs[kk][tx * 8];
            *(float4*)&rb[4] = *(float4*)&Bs[kk][tx * 8 + 4];
#pragma unroll
            for (int i = 0; i < 8; i++)
#pragma unroll
                for (int j = 0; j < 8; j++) c[i][j] += ra[i] * rb[j];
        }
    }

#pragma unroll
    for (int i = 0; i < 8; i++) {
        int grow = row0 + ty * 8 + i;
        int colb = col0 + tx * 8;
        float4 v0 = make_float4(c[i][0] + bias[colb + 0], c[i][1] + bias[colb + 1],
                                c[i][2] + bias[colb + 2], c[i][3] + bias[colb + 3]);
        float4 v1 = make_float4(c[i][4] + bias[colb + 4], c[i][5] + bias[colb + 5],
                                c[i][6] + bias[colb + 6], c[i][7] + bias[colb + 7]);
        *(float4*)&out[grow * 512 + colb]     = v0;
        *(float4*)&out[grow * 512 + colb + 4] = v1;
    }
}

// ---------------------------------------------------------------------------
// Fused attention: per block = (b,h, 8-query tile).
// Computes dots0/dots rows in registers, both softmaxes, dynamic threshold
// pruning, attn0 output, and the AV product.
// ---------------------------------------------------------------------------
__global__ __launch_bounds__(256) void attn_kernel(
    const float* __restrict__ prob,
    const float* __restrict__ t1,
    const float* __restrict__ t2,
    const float* __restrict__ sita,
    const float* __restrict__ Wth,
    float* __restrict__ attn0_out)
{
    __shared__ float qs[QT][64];
    __shared__ float wt[64];
    __shared__ float exA[64];                 // 63 used
    __shared__ float traw[QT];
    __shared__ float red[3][QT][8];
    __shared__ float fin_m0[QT], fin_is0[QT], fin_mB[QT], fin_isB[QT];
    __shared__ float fin_mn[QT], fin_thr[QT], fin_id[QT], fin_gate[QT];
    __shared__ union UU {
        float prodt[3969];                    // bias table (scores phase)
        float attnp[QT][1024];                // pruned attention (AV phase)
    } U;

    const int t    = threadIdx.x;
    const int lane = t & 31, wid = t >> 5;
    const int bh = blockIdx.y;
    const int b  = bh >> 3, h = bh & 7;
    const int i0 = blockIdx.x * QT;
    const float scale = 0.125f;               // 64^-0.5

    // ---- stage smem tables ----
    {
        float st = sita[h];
        float factor = 1.0f / (2.0f * st * st + 1e-6f);
        if (t < 63) {
            float dd = (float)(t - 31);
            exA[t] = __expf(-factor * dd * dd * (1.0f / 1024.0f));
        }
    }
    for (int e = t; e < 3969; e += 256)
        U.prodt[e] = t1[e * 8 + h] * t2[e * 8 + h];
    for (int e = t; e < QT * 64; e += 256)
        qs[e >> 6][e & 63] = g_Q[((bh * 1024) + i0 + (e >> 6)) * 64 + (e & 63)];
    if (t < 64) wt[t] = Wth[t];
    __syncthreads();

    // ---- per-query threshold raw value: sigmoid(q . W_thresh)*sigmoid(-2) ----
    {
        int q = wid;  // 8 warps, 8 queries
        float v = qs[q][lane] * wt[lane] + qs[q][lane + 32] * wt[lane + 32];
#pragma unroll
        for (int o = 16; o; o >>= 1) v += __shfl_xor_sync(0xffffffffu, v, o);
        if (lane == 0) {
            float sg = 1.0f / (1.0f + __expf(-v));
            traw[q] = sg * 0.11920292202211755f;   // sigmoid(-2.0)
        }
    }

    // ---- scores: thread owns j = 4t..4t+3, loop over d (coalesced K^T) ----
    float d0[QT][4];
#pragma unroll
    for (int q = 0; q < QT; q++)
#pragma unroll
        for (int r = 0; r < 4; r++) d0[q][r] = 0.f;

    const float* Kp = &g_Kt[(bh * 64) * 1024 + 4 * t];
#pragma unroll 4
    for (int d = 0; d < 64; d++) {
        float4 kv = *(const float4*)&Kp[d * 1024];
#pragma unroll
        for (int q = 0; q < QT; q++) {
            float qv = qs[q][d];
            d0[q][0] += qv * kv.x; d0[q][1] += qv * kv.y;
            d0[q][2] += qv * kv.z; d0[q][3] += qv * kv.w;
        }
    }

    // epilogue: scale, + bias + 0.01*pos  (rel_index/dis computed analytically)
    float dB[QT][4];
    const int ri  = i0 >> 5;
    const int ci0 = i0 & 31;
#pragma unroll
    for (int r = 0; r < 4; r++) {
        int j  = 4 * t + r;
        int rj = j >> 5, cj = j & 31;
        int di = ri - rj;
        float eA = exA[di + 31];
        const float* prow = &U.prodt[(di + 31) * 63];
#pragma unroll
        for (int q = 0; q < QT; q++) {
            int dj = ci0 + q - cj;
            float s0 = d0[q][r] * scale;
            d0[q][r] = s0;
            dB[q][r] = s0 + prow[dj + 31] + 0.01f * (eA * exA[dj + 31]);
        }
    }

    // ---- round 1: max(dots0), max(dots), min(dots) ----
#pragma unroll
    for (int q = 0; q < QT; q++) {
        float m0 = fmaxf(fmaxf(d0[q][0], d0[q][1]), fmaxf(d0[q][2], d0[q][3]));
        float mB = fmaxf(fmaxf(dB[q][0], dB[q][1]), fmaxf(dB[q][2], dB[q][3]));
        float mn = fminf(fminf(dB[q][0], dB[q][1]), fminf(dB[q][2], dB[q][3]));
#pragma unroll
        for (int o = 16; o; o >>= 1) {
            m0 = fmaxf(m0, __shfl_xor_sync(0xffffffffu, m0, o));
            mB = fmaxf(mB, __shfl_xor_sync(0xffffffffu, mB, o));
            mn = fminf(mn, __shfl_xor_sync(0xffffffffu, mn, o));
        }
        if (lane == 0) { red[0][q][wid] = m0; red[1][q][wid] = mB; red[2][q][wid] = mn; }
    }
    __syncthreads();
    if (t < QT) {
        float m0 = -1e30f, mB = -1e30f, mn = 1e30f;
#pragma unroll
        for (int w = 0; w < 8; w++) {
            m0 = fmaxf(m0, red[0][t][w]);
            mB = fmaxf(mB, red[1][t][w]);
            mn = fminf(mn, red[2][t][w]);
        }
        fin_m0[t] = m0; fin_mB[t] = mB; fin_mn[t] = mn;
    }
    __syncthreads();

    // ---- round 2: exp + sums; finalize softmax scales, threshold, gate ----
#pragma unroll
    for (int q = 0; q < QT; q++) {
        float m0 = fin_m0[q], mB = fin_mB[q];
        float s0 = 0.f, sB = 0.f;
#pragma unroll
        for (int r = 0; r < 4; r++) {
            d0[q][r] = __expf(d0[q][r] - m0); s0 += d0[q][r];
            dB[q][r] = __expf(dB[q][r] - mB); sB += dB[q][r];
        }
#pragma unroll
        for (int o = 16; o; o >>= 1) {
            s0 += __shfl_xor_sync(0xffffffffu, s0, o);
            sB += __shfl_xor_sync(0xffffffffu, sB, o);
        }
        if (lane == 0) { red[0][q][wid] = s0; red[1][q][wid] = sB; }
    }
    __syncthreads();
    if (t < QT) {
        float s0 = 0.f, sB = 0.f;
#pragma unroll
        for (int w = 0; w < 8; w++) { s0 += red[0][t][w]; sB += red[1][t][w]; }
        float is0 = 1.0f / s0;
        float isB = 1.0f / sB;
        fin_is0[t] = is0; fin_isB[t] = isB;
        float amax = isB;                                   // exp(mB-mB)/sB
        float amin = __expf(fin_mn[t] - fin_mB[t]) * isB;
        fin_thr[t]  = amin + traw[t] * (amax - amin);
        fin_gate[t] = (prob[b * 1024 + i0 + t] >= 0.9f) ? 0.0f : 1.0f;
    }
    __syncthreads();

    // ---- write attn0 = softmax(dots0) ----
#pragma unroll
    for (int q = 0; q < QT; q++) {
        float is0 = fin_is0[q];
        float4 v = make_float4(d0[q][0] * is0, d0[q][1] * is0,
                               d0[q][2] * is0, d0[q][3] * is0);
        *(float4*)&attn0_out[(size_t)(bh * 1024 + i0 + q) * 1024 + 4 * t] = v;
    }

    // ---- round 3: record + deno, then pruned attention into smem ----
#pragma unroll
    for (int q = 0; q < QT; q++) {
        float isB = fin_isB[q], th = fin_thr[q], gt = fin_gate[q];
        float s = 0.f;
#pragma unroll
        for (int r = 0; r < 4; r++) {
            float a  = dB[q][r] * isB;                 // attn value
            float ar = (a > th) ? a * gt : 0.0f;       // attn * record
            dB[q][r] = ar;
            s += ar;
        }
#pragma unroll
        for (int o = 16; o; o >>= 1) s += __shfl_xor_sync(0xffffffffu, s, o);
        if (lane == 0) red[0][q][wid] = s;
    }
    __syncthreads();
    if (t < QT) {
        float s = 0.f;
#pragma unroll
        for (int w = 0; w < 8; w++) s += red[0][t][w];
        fin_id[t] = 1.0f / (s + 1e-6f);
    }
    __syncthreads();
#pragma unroll
    for (int q = 0; q < QT; q++) {
        float idn = fin_id[q];
        float4 v = make_float4(dB[q][0] * idn, dB[q][1] * idn,
                               dB[q][2] * idn, dB[q][3] * idn);
        *(float4*)&U.attnp[q][4 * t] = v;              // prodt dead since round-1 sync
    }
    __syncthreads();

    // ---- AV: out[q][d] = sum_j attnp[q][j] * V[j][d] ----
    const int d  = t & 63;
    const int js = t >> 6;        // 4 j-slices of 256
    float acc[QT];
#pragma unroll
    for (int q = 0; q < QT; q++) acc[q] = 0.f;
    const float* Vp = &g_V[(size_t)bh * 1024 * 64 + d];
    for (int jj = js * 256; jj < js * 256 + 256; jj += 4) {
        float4 a[QT];
#pragma unroll
        for (int q = 0; q < QT; q++) a[q] = *(const float4*)&U.attnp[q][jj];
#pragma unroll
        for (int r = 0; r < 4; r++) {
            float v = Vp[(jj + r) * 64];
#pragma unroll
            for (int q = 0; q < QT; q++) {
                float aq = (r == 0) ? a[q].x : (r == 1) ? a[q].y : (r == 2) ? a[q].z : a[q].w;
                acc[q] += aq * v;
            }
        }
    }
    __syncthreads();
    float* osum = (float*)&U;     // attnp reads complete; reuse region
#pragma unroll
    for (int q = 0; q < QT; q++) osum[(js * QT + q) * 64 + d] = acc[q];
    __syncthreads();
    for (int o = t; o < QT * 64; o += 256) {
        int q = o >> 6, dd = o & 63;
        float v = osum[(0 * QT + q) * 64 + dd] + osum[(1 * QT + q) * 64 + dd]
                + osum[(2 * QT + q) * 64 + dd] + osum[(3 * QT + q) * 64 + dd];
        g_O[((size_t)b * 1024 + i0 + q) * 512 + h * 64 + dd] = v;
    }
}

// ---------------------------------------------------------------------------
extern "C" void kernel_launch(void* const* d_in, const int* in_sizes, int n_in,
                              void* d_out, int out_size)
{
    const float* x    = (const float*)d_in[0];
    const float* prob = (const float*)d_in[1];
    const float* Wqkv = (const float*)d_in[2];
    const float* t1   = (const float*)d_in[3];
    const float* t2   = (const float*)d_in[4];
    const float* sita = (const float*)d_in[5];
    const float* Wth  = (const float*)d_in[6];
    const float* Wout = (const float*)d_in[7];
    const float* bout = (const float*)d_in[8];
    // d_in[9] = rel_index, d_in[10] = dis : computed analytically, unused.

    float* out   = (float*)d_out;
    float* attn0 = out + (size_t)Bq * Nn * DIMM;   // outputs concatenated (out, attn0)

    qkv_gemm<<<dim3(12, 32), 256>>>(x, Wqkv);
    attn_kernel<<<dim3(Nn / QT, BH), 256>>>(prob, t1, t2, sita, Wth, attn0);
    out_gemm<<<dim3(4, 32), 256>>>(Wout, bout, out);
}

// round 13
// speedup vs baseline: 1.2301x; 1.2301x over previous
#include <cuda_runtime.h>
#include <cstdint>

#define Bq 4
#define Hh 8
#define Nn 1024
#define Dd 64
#define DIMM 512
#define BH (Bq*Hh)
#define QT 8

// scratch (8 MB each)
__device__ float g_Q [BH*Nn*Dd];
__device__ float g_Kt[BH*Dd*Nn];
__device__ float g_V [BH*Nn*Dd];
__device__ float g_O [Bq*Nn*DIMM];

__device__ __forceinline__ uint32_t f2tf(float f) {
    uint32_t u;
    asm("cvt.rna.tf32.f32 %0, %1;" : "=r"(u) : "f"(f));
    return u;
}

#define MMA_TF32(c, a, b)                                                       \
    asm volatile(                                                               \
        "mma.sync.aligned.m16n8k8.row.col.f32.tf32.tf32.f32 "                   \
        "{%0,%1,%2,%3},{%4,%5,%6,%7},{%8,%9},{%0,%1,%2,%3};"                    \
        : "+f"((c)[0]), "+f"((c)[1]), "+f"((c)[2]), "+f"((c)[3])                \
        : "r"((a)[0]), "r"((a)[1]), "r"((a)[2]), "r"((a)[3]),                   \
          "r"((b)[0]), "r"((b)[1]))

// ---------------------------------------------------------------------------
// 3xTF32 split-precision tensor GEMM: C(4096 x NCOLS) = A(4096x512) @ B(512xNCOLS)
// fp32-equivalent accuracy: a = a_hi + a_lo (tf32 split), accumulate
// a_hi*b_hi + a_lo*b_hi + a_hi*b_lo. Block 128x128xK16, 8 warps (4Mx2N).
// Fragments staged fragment-major as raw fp32 in smem (layout verified R12);
// the tf32 split happens at fragment-load time.
// MODE 0: scatter into g_Q / g_Kt / g_V ; MODE 1: out = C + bias
// ---------------------------------------------------------------------------
template<int NCOLS, int MODE>
__global__ __launch_bounds__(256) void mm_3xtf32_kernel(const float* __restrict__ A,
                                                        const float* __restrict__ B,
                                                        const float* __restrict__ bias,
                                                        float* __restrict__ out)
{
    __shared__ float sA[2][2][8][4][33];   // [buf][kt][mt][reg][lane pad33]
    __shared__ float sB[2][2][16][2][33];  // [buf][kt][nt][reg][lane pad33]

    const int t    = threadIdx.x;
    const int lane = t & 31, w = t >> 5;
    const int wm = w >> 1, wn = w & 1;        // 4 x 2 warp grid
    const int m0 = blockIdx.y * 128;
    const int n0 = blockIdx.x * 128;

    float acc[2][8][4];
#pragma unroll
    for (int i = 0; i < 2; i++)
#pragma unroll
        for (int j = 0; j < 8; j++)
#pragma unroll
            for (int e = 0; e < 4; e++) acc[i][j][e] = 0.f;

    // ---- loader indexing (layout verified in R12) ----
    const int aRow  = t >> 1;
    const int aKt   = t & 1;
    const int amt   = aRow >> 4;
    const int aRegB = (aRow & 15) >> 3;
    const int aLnB  = (aRow & 7) << 2;
    const float* aG = A + (m0 + aRow) * 512 + aKt * 8;

    const int bK    = t >> 5;                 // 0..7
    const int bReg  = bK >> 2;
    const int bKlo  = bK & 3;
    const int bNt   = (t & 31) >> 1;
    const int bLnB  = (t & 1) * 16 + bKlo;
    const float* bG = B + bK * NCOLS + n0 + (t & 31) * 4;

    float4 aV0 = *(const float4*)aG;
    float4 aV1 = *(const float4*)(aG + 4);
    float4 bV0 = *(const float4*)bG;
    float4 bV1 = *(const float4*)(bG + 8 * NCOLS);

    for (int it = 0; it < 32; it++) {
        const int buf = it & 1;
        sA[buf][aKt][amt][aRegB + 0][aLnB + 0] = aV0.x;
        sA[buf][aKt][amt][aRegB + 0][aLnB + 1] = aV0.y;
        sA[buf][aKt][amt][aRegB + 0][aLnB + 2] = aV0.z;
        sA[buf][aKt][amt][aRegB + 0][aLnB + 3] = aV0.w;
        sA[buf][aKt][amt][aRegB + 2][aLnB + 0] = aV1.x;
        sA[buf][aKt][amt][aRegB + 2][aLnB + 1] = aV1.y;
        sA[buf][aKt][amt][aRegB + 2][aLnB + 2] = aV1.z;
        sA[buf][aKt][amt][aRegB + 2][aLnB + 3] = aV1.w;
        sB[buf][0][bNt][bReg][bLnB +  0] = bV0.x;
        sB[buf][0][bNt][bReg][bLnB +  4] = bV0.y;
        sB[buf][0][bNt][bReg][bLnB +  8] = bV0.z;
        sB[buf][0][bNt][bReg][bLnB + 12] = bV0.w;
        sB[buf][1][bNt][bReg][bLnB +  0] = bV1.x;
        sB[buf][1][bNt][bReg][bLnB +  4] = bV1.y;
        sB[buf][1][bNt][bReg][bLnB +  8] = bV1.z;
        sB[buf][1][bNt][bReg][bLnB + 12] = bV1.w;
        __syncthreads();

        if (it + 1 < 32) {
            aG += 16; bG += 16 * NCOLS;
            aV0 = *(const float4*)aG;
            aV1 = *(const float4*)(aG + 4);
            bV0 = *(const float4*)bG;
            bV1 = *(const float4*)(bG + 8 * NCOLS);
        }

#pragma unroll
        for (int kt = 0; kt < 2; kt++) {
            uint32_t ah[2][4], al[2][4], bh[8][2], bl[8][2];
#pragma unroll
            for (int mt = 0; mt < 2; mt++)
#pragma unroll
                for (int r = 0; r < 4; r++) {
                    float v = sA[buf][kt][wm * 2 + mt][r][lane];
                    uint32_t h = f2tf(v);
                    ah[mt][r] = h;
                    al[mt][r] = f2tf(v - __uint_as_float(h));
                }
#pragma unroll
            for (int nt = 0; nt < 8; nt++)
#pragma unroll
                for (int r = 0; r < 2; r++) {
                    float v = sB[buf][kt][wn * 8 + nt][r][lane];
                    uint32_t h = f2tf(v);
                    bh[nt][r] = h;
                    bl[nt][r] = f2tf(v - __uint_as_float(h));
                }
#pragma unroll
            for (int mt = 0; mt < 2; mt++)
#pragma unroll
                for (int nt = 0; nt < 8; nt++) {
                    MMA_TF32(acc[mt][nt], al[mt], bh[nt]);   // small terms first
                    MMA_TF32(acc[mt][nt], ah[mt], bl[nt]);
                    MMA_TF32(acc[mt][nt], ah[mt], bh[nt]);
                }
        }
    }

    // ---- epilogue ----
    const int r0 = lane >> 2;
    const int cc = (lane & 3) * 2;
#pragma unroll
    for (int mt = 0; mt < 2; mt++) {
#pragma unroll
        for (int nt = 0; nt < 8; nt++) {
            int gcol = n0 + wn * 64 + nt * 8 + cc;
#pragma unroll
            for (int half = 0; half < 2; half++) {
                int grow = m0 + wm * 32 + mt * 16 + r0 + half * 8;
                float v0 = acc[mt][nt][half * 2 + 0];
                float v1 = acc[mt][nt][half * 2 + 1];
                if (MODE == 1) {
                    float2 o = make_float2(v0 + bias[gcol], v1 + bias[gcol + 1]);
                    *(float2*)&out[grow * 512 + gcol] = o;
                } else {
                    int b = grow >> 10, n = grow & 1023;
                    int h = (gcol >> 6) & 7, d = gcol & 63;
                    int bh = b * 8 + h;
                    int part = gcol >> 9;
                    if (part == 0) {
                        *(float2*)&g_Q[(bh * 1024 + n) * 64 + d] = make_float2(v0, v1);
                    } else if (part == 1) {
                        g_Kt[(bh * 64 + d) * 1024 + n]     = v0;
                        g_Kt[(bh * 64 + d + 1) * 1024 + n] = v1;
                    } else {
                        *(float2*)&g_V[(bh * 1024 + n) * 64 + d] = make_float2(v0, v1);
                    }
                }
            }
        }
    }
}

// ---------------------------------------------------------------------------
// Fused attention: per block = (b,h, 8-query tile). Identical to R11 pass.
// ---------------------------------------------------------------------------
__global__ __launch_bounds__(256) void attn_kernel(
    const float* __restrict__ prob,
    const float* __restrict__ t1,
    const float* __restrict__ t2,
    const float* __restrict__ sita,
    const float* __restrict__ Wth,
    float* __restrict__ attn0_out)
{
    __shared__ float qs[QT][64];
    __shared__ float wt[64];
    __shared__ float exA[64];
    __shared__ float traw[QT];
    __shared__ float red[3][QT][8];
    __shared__ float fin_m0[QT], fin_is0[QT], fin_mB[QT], fin_isB[QT];
    __shared__ float fin_mn[QT], fin_thr[QT], fin_id[QT], fin_gate[QT];
    __shared__ union UU {
        float prodt[3969];
        float attnp[QT][1024];
    } U;

    const int t    = threadIdx.x;
    const int lane = t & 31, wid = t >> 5;
    const int bh = blockIdx.y;
    const int b  = bh >> 3, h = bh & 7;
    const int i0 = blockIdx.x * QT;
    const float scale = 0.125f;

    {
        float st = sita[h];
        float factor = 1.0f / (2.0f * st * st + 1e-6f);
        if (t < 63) {
            float dd = (float)(t - 31);
            exA[t] = __expf(-factor * dd * dd * (1.0f / 1024.0f));
        }
    }
    for (int e = t; e < 3969; e += 256)
        U.prodt[e] = t1[e * 8 + h] * t2[e * 8 + h];
    for (int e = t; e < QT * 64; e += 256)
        qs[e >> 6][e & 63] = g_Q[((bh * 1024) + i0 + (e >> 6)) * 64 + (e & 63)];
    if (t < 64) wt[t] = Wth[t];
    __syncthreads();

    {
        int q = wid;
        float v = qs[q][lane] * wt[lane] + qs[q][lane + 32] * wt[lane + 32];
#pragma unroll
        for (int o = 16; o; o >>= 1) v += __shfl_xor_sync(0xffffffffu, v, o);
        if (lane == 0) {
            float sg = 1.0f / (1.0f + __expf(-v));
            traw[q] = sg * 0.11920292202211755f;
        }
    }

    float d0[QT][4];
#pragma unroll
    for (int q = 0; q < QT; q++)
#pragma unroll
        for (int r = 0; r < 4; r++) d0[q][r] = 0.f;

    const float* Kp = &g_Kt[(bh * 64) * 1024 + 4 * t];
#pragma unroll 4
    for (int d = 0; d < 64; d++) {
        float4 kv = *(const float4*)&Kp[d * 1024];
#pragma unroll
        for (int q = 0; q < QT; q++) {
            float qv = qs[q][d];
            d0[q][0] += qv * kv.x; d0[q][1] += qv * kv.y;
            d0[q][2] += qv * kv.z; d0[q][3] += qv * kv.w;
        }
    }

    float dB[QT][4];
    const int ri  = i0 >> 5;
    const int ci0 = i0 & 31;
#pragma unroll
    for (int r = 0; r < 4; r++) {
        int j  = 4 * t + r;
        int rj = j >> 5, cj = j & 31;
        int di = ri - rj;
        float eA = exA[di + 31];
        const float* prow = &U.prodt[(di + 31) * 63];
#pragma unroll
        for (int q = 0; q < QT; q++) {
            int dj = ci0 + q - cj;
            float s0 = d0[q][r] * scale;
            d0[q][r] = s0;
            dB[q][r] = s0 + prow[dj + 31] + 0.01f * (eA * exA[dj + 31]);
        }
    }

#pragma unroll
    for (int q = 0; q < QT; q++) {
        float m0 = fmaxf(fmaxf(d0[q][0], d0[q][1]), fmaxf(d0[q][2], d0[q][3]));
        float mB = fmaxf(fmaxf(dB[q][0], dB[q][1]), fmaxf(dB[q][2], dB[q][3]));
        float mn = fminf(fminf(dB[q][0], dB[q][1]), fminf(dB[q][2], dB[q][3]));
#pragma unroll
        for (int o = 16; o; o >>= 1) {
            m0 = fmaxf(m0, __shfl_xor_sync(0xffffffffu, m0, o));
            mB = fmaxf(mB, __shfl_xor_sync(0xffffffffu, mB, o));
            mn = fminf(mn, __shfl_xor_sync(0xffffffffu, mn, o));
        }
        if (lane == 0) { red[0][q][wid] = m0; red[1][q][wid] = mB; red[2][q][wid] = mn; }
    }
    __syncthreads();
    if (t < QT) {
        float m0 = -1e30f, mB = -1e30f, mn = 1e30f;
#pragma unroll
        for (int w = 0; w < 8; w++) {
            m0 = fmaxf(m0, red[0][t][w]);
            mB = fmaxf(mB, red[1][t][w]);
            mn = fminf(mn, red[2][t][w]);
        }
        fin_m0[t] = m0; fin_mB[t] = mB; fin_mn[t] = mn;
    }
    __syncthreads();

#pragma unroll
    for (int q = 0; q < QT; q++) {
        float m0 = fin_m0[q], mB = fin_mB[q];
        float s0 = 0.f, sB = 0.f;
#pragma unroll
        for (int r = 0; r < 4; r++) {
            d0[q][r] = __expf(d0[q][r] - m0); s0 += d0[q][r];
            dB[q][r] = __expf(dB[q][r] - mB); sB += dB[q][r];
        }
#pragma unroll
        for (int o = 16; o; o >>= 1) {
            s0 += __shfl_xor_sync(0xffffffffu, s0, o);
            sB += __shfl_xor_sync(0xffffffffu, sB, o);
        }
        if (lane == 0) { red[0][q][wid] = s0; red[1][q][wid] = sB; }
    }
    __syncthreads();
    if (t < QT) {
        float s0 = 0.f, sB = 0.f;
#pragma unroll
        for (int w = 0; w < 8; w++) { s0 += red[0][t][w]; sB += red[1][t][w]; }
        float is0 = 1.0f / s0;
        float isB = 1.0f / sB;
        fin_is0[t] = is0; fin_isB[t] = isB;
        float amax = isB;
        float amin = __expf(fin_mn[t] - fin_mB[t]) * isB;
        fin_thr[t]  = amin + traw[t] * (amax - amin);
        fin_gate[t] = (prob[b * 1024 + i0 + t] >= 0.9f) ? 0.0f : 1.0f;
    }
    __syncthreads();

#pragma unroll
    for (int q = 0; q < QT; q++) {
        float is0 = fin_is0[q];
        float4 v = make_float4(d0[q][0] * is0, d0[q][1] * is0,
                               d0[q][2] * is0, d0[q][3] * is0);
        *(float4*)&attn0_out[(size_t)(bh * 1024 + i0 + q) * 1024 + 4 * t] = v;
    }

#pragma unroll
    for (int q = 0; q < QT; q++) {
        float isB = fin_isB[q], th = fin_thr[q], gt = fin_gate[q];
        float s = 0.f;
#pragma unroll
        for (int r = 0; r < 4; r++) {
            float a  = dB[q][r] * isB;
            float ar = (a > th) ? a * gt : 0.0f;
            dB[q][r] = ar;
            s += ar;
        }
#pragma unroll
        for (int o = 16; o; o >>= 1) s += __shfl_xor_sync(0xffffffffu, s, o);
        if (lane == 0) red[0][q][wid] = s;
    }
    __syncthreads();
    if (t < QT) {
        float s = 0.f;
#pragma unroll
        for (int w = 0; w < 8; w++) s += red[0][t][w];
        fin_id[t] = 1.0f / (s + 1e-6f);
    }
    __syncthreads();
#pragma unroll
    for (int q = 0; q < QT; q++) {
        float idn = fin_id[q];
        float4 v = make_float4(dB[q][0] * idn, dB[q][1] * idn,
                               dB[q][2] * idn, dB[q][3] * idn);
        *(float4*)&U.attnp[q][4 * t] = v;
    }
    __syncthreads();

    const int d  = t & 63;
    const int js = t >> 6;
    float acc[QT];
#pragma unroll
    for (int q = 0; q < QT; q++) acc[q] = 0.f;
    const float* Vp = &g_V[(size_t)bh * 1024 * 64 + d];
    for (int jj = js * 256; jj < js * 256 + 256; jj += 4) {
        float4 a[QT];
#pragma unroll
        for (int q = 0; q < QT; q++) a[q] = *(const float4*)&U.attnp[q][jj];
#pragma unroll
        for (int r = 0; r < 4; r++) {
            float v = Vp[(jj + r) * 64];
#pragma unroll
            for (int q = 0; q < QT; q++) {
                float aq = (r == 0) ? a[q].x : (r == 1) ? a[q].y : (r == 2) ? a[q].z : a[q].w;
                acc[q] += aq * v;
            }
        }
    }
    __syncthreads();
    float* osum = (float*)&U;
#pragma unroll
    for (int q = 0; q < QT; q++) osum[(js * QT + q) * 64 + d] = acc[q];
    __syncthreads();
    for (int o = t; o < QT * 64; o += 256) {
        int q = o >> 6, dd = o & 63;
        float v = osum[(0 * QT + q) * 64 + dd] + osum[(1 * QT + q) * 64 + dd]
                + osum[(2 * QT + q) * 64 + dd] + osum[(3 * QT + q) * 64 + dd];
        g_O[((size_t)b * 1024 + i0 + q) * 512 + h * 64 + dd] = v;
    }
}

// ---------------------------------------------------------------------------
extern "C" void kernel_launch(void* const* d_in, const int* in_sizes, int n_in,
                              void* d_out, int out_size)
{
    const float* x    = (const float*)d_in[0];
    const float* prob = (const float*)d_in[1];
    const float* Wqkv = (const float*)d_in[2];
    const float* t1   = (const float*)d_in[3];
    const float* t2   = (const float*)d_in[4];
    const float* sita = (const float*)d_in[5];
    const float* Wth  = (const float*)d_in[6];
    const float* Wout = (const float*)d_in[7];
    const float* bout = (const float*)d_in[8];

    float* out   = (float*)d_out;
    float* attn0 = out + (size_t)Bq * Nn * DIMM;

    float* gO;
    cudaGetSymbolAddress((void**)&gO, g_O);

    mm_3xtf32_kernel<1536, 0><<<dim3(12, 32), 256>>>(x, Wqkv, nullptr, nullptr);
    attn_kernel<<<dim3(Nn / QT, BH), 256>>>(prob, t1, t2, sita, Wth, attn0);
    mm_3xtf32_kernel<512, 1><<<dim3(4, 32), 256>>>(gO, Wout, bout, out);
}